// round 2
// baseline (speedup 1.0000x reference)
#include <cuda_runtime.h>

#define NNODES 50000
#define NHEADS 8
#define EPS 1e-8f
#define ATT_NORM 2.0f

// Scratch: per-(node, head) running max of nj, stored as float (compared via
// int bits — valid because all values are >= 0 and the init value is 0.0f).
__device__ float g_node_max[NNODES * NHEADS];

__global__ void zero_node_max() {
    int i = blockIdx.x * blockDim.x + threadIdx.x;
    if (i < NNODES * NHEADS) g_node_max[i] = 0.0f;
}

// One thread per (edge, head). Loads 16 floats (64B) of x_j via 4x float4,
// computes nj = ||x_j|| + eps, scatter-max into g_node_max[node*H + h].
__global__ void scatter_max_kernel(const float4* __restrict__ x_j,
                                   const int* __restrict__ index,
                                   int eh_total) {
    int t = blockIdx.x * blockDim.x + threadIdx.x;
    if (t >= eh_total) return;
    int e = t >> 3;          // H == 8
    int h = t & 7;

    const float4* p = x_j + (size_t)t * 4;
    float s = 0.0f;
#pragma unroll
    for (int k = 0; k < 4; ++k) {
        float4 v = p[k];
        s += v.x * v.x + v.y * v.y + v.z * v.z + v.w * v.w;
    }
    float nj = sqrtf(s) + EPS;

    int node = index[e];
    if ((unsigned)node < NNODES)   // guard: degrade to wrong-answer, not crash
        atomicMax((int*)&g_node_max[node * NHEADS + h], __float_as_int(nj));
}

// One thread per (edge, head). ni from x_i, gather segmax, divide, clip.
__global__ void finalize_kernel(const float* __restrict__ e_ij,
                                const float4* __restrict__ x_i,
                                const int* __restrict__ index,
                                float* __restrict__ out,
                                int eh_total) {
    int t = blockIdx.x * blockDim.x + threadIdx.x;
    if (t >= eh_total) return;
    int e = t >> 3;
    int h = t & 7;

    const float4* p = x_i + (size_t)t * 4;
    float s = 0.0f;
#pragma unroll
    for (int k = 0; k < 4; ++k) {
        float4 v = p[k];
        s += v.x * v.x + v.y * v.y + v.z * v.z + v.w * v.w;
    }
    float ni = sqrtf(s) + EPS;

    int node = index[e];
    float m = 0.0f;
    if ((unsigned)node < NNODES)
        m = g_node_max[node * NHEADS + h];
    m += EPS;                                   // segmax result + EPS (per reference)
    float denom = ATT_NORM * (ni + m) + EPS;

    float r = e_ij[t] / denom;
    r = fminf(10.0f, fmaxf(-10.0f, r));
    out[t] = r;
}

extern "C" void kernel_launch(void* const* d_in, const int* in_sizes, int n_in,
                              void* d_out, int out_size) {
    // metadata order: e_ij [E,H] f32, x_i [E,H,D] f32, x_j [E,H,D] f32, index [E]
    // NOTE: index is int32 on disk (JAX x64 disabled demotes int64 -> int32).
    const float*  e_ij  = (const float*)d_in[0];
    const float4* x_i   = (const float4*)d_in[1];
    const float4* x_j   = (const float4*)d_in[2];
    const int*    index = (const int*)d_in[3];
    float*        out   = (float*)d_out;

    int eh_total = in_sizes[0];          // E * H = 6,400,000

    const int B = 256;
    zero_node_max<<<(NNODES * NHEADS + B - 1) / B, B>>>();
    scatter_max_kernel<<<(eh_total + B - 1) / B, B>>>(x_j, index, eh_total);
    finalize_kernel<<<(eh_total + B - 1) / B, B>>>(e_ij, x_i, index, out, eh_total);
}